// round 4
// baseline (speedup 1.0000x reference)
#include <cuda_runtime.h>
#include <cuda_bf16.h>

// Problem constants
#define PW 32
#define PL 64
#define PK 512
#define PN 64
#define ROWS_PER_W (PL * PK)            // 32768
#define TOTAL_ROWS (PW * ROWS_PER_W)    // 1048576
#define EN_ELEMS   TOTAL_ROWS
#define MASK_ELEMS (PW * (PL - 1) * PK) // 1032192

// Scratch (no allocs allowed -> __device__ globals)
__device__ unsigned char       g_mask[MASK_ELEMS];
__device__ unsigned long long  g_packed[TOTAL_ROWS];   // 8 MB: states rows as 64-bit masks

#define QT_STRIDE 72  // halves; padded -> conflict-free column reads

__device__ __forceinline__ unsigned pack_bf16(float lo, float hi) {
    __nv_bfloat162 h = __floats2bfloat162_rn(lo, hi);
    return *reinterpret_cast<unsigned*>(&h);
}

__device__ __forceinline__ void mma_bf16(float* d, const unsigned* a, unsigned b0, unsigned b1) {
    asm volatile(
        "mma.sync.aligned.m16n8k16.row.col.f32.bf16.bf16.f32 "
        "{%0,%1,%2,%3}, {%4,%5,%6,%7}, {%8,%9}, {%0,%1,%2,%3};"
        : "+f"(d[0]), "+f"(d[1]), "+f"(d[2]), "+f"(d[3])
        : "r"(a[0]), "r"(a[1]), "r"(a[2]), "r"(a[3]), "r"(b0), "r"(b1));
}

// ---------------------------------------------------------------------------
// Kernel 1: energies via bf16-split MMA. Warp tile = 32 rows x 64 cols
// (two 16-row blocks sharing every B-fragment load -> half the LDS traffic).
// Also packs each state row into a 64-bit mask for the swap kernel.
// ---------------------------------------------------------------------------
__global__ void __launch_bounds__(256, 2)
energies_kernel(const float* __restrict__ states,
                const float* __restrict__ Qg,
                float* __restrict__ energies_out) {
    const int w   = blockIdx.y;    // 0..31
    const int cta = blockIdx.x;    // 0..127
    const int tid = threadIdx.x;

    __shared__ __nv_bfloat16 sQT[3][PN * QT_STRIDE];

    const float* Qw = Qg + (size_t)w * PN * PN;
    for (int idx = tid; idx < PN * PN; idx += 256) {
        const int i = idx >> 6;
        const int j = idx & 63;
        float q = Qw[idx];
        __nv_bfloat16 h = __float2bfloat16(q);
        float r = q - __bfloat162float(h);
        __nv_bfloat16 m = __float2bfloat16(r);
        float r2 = r - __bfloat162float(m);
        __nv_bfloat16 lo = __float2bfloat16(r2);
        sQT[0][j * QT_STRIDE + i] = h;
        sQT[1][j * QT_STRIDE + i] = m;
        sQT[2][j * QT_STRIDE + i] = lo;
    }
    __syncthreads();

    const int warp = tid >> 5;
    const int lane = tid & 31;
    const int g  = lane >> 2;  // 0..7
    const int tg = lane & 3;   // 0..3

    const int row_base = w * ROWS_PER_W + cta * 256 + warp * 32;

    // A fragments for both 16-row blocks, all 4 k-chunks
    unsigned af[2][4][4];
    #pragma unroll
    for (int bi = 0; bi < 2; bi++) {
        const float* rowg  = states + (size_t)(row_base + bi * 16 + g) * PN;
        const float* rowg8 = rowg + 8 * PN;
        #pragma unroll
        for (int kc = 0; kc < 4; kc++) {
            const int c0 = kc * 16 + tg * 2;
            float2 v;
            v = *reinterpret_cast<const float2*>(rowg  + c0);     af[bi][kc][0] = pack_bf16(v.x, v.y);
            v = *reinterpret_cast<const float2*>(rowg8 + c0);     af[bi][kc][1] = pack_bf16(v.x, v.y);
            v = *reinterpret_cast<const float2*>(rowg  + c0 + 8); af[bi][kc][2] = pack_bf16(v.x, v.y);
            v = *reinterpret_cast<const float2*>(rowg8 + c0 + 8); af[bi][kc][3] = pack_bf16(v.x, v.y);
        }
    }

    float d[2][8][4];
    #pragma unroll
    for (int bi = 0; bi < 2; bi++)
        #pragma unroll
        for (int nt = 0; nt < 8; nt++)
            #pragma unroll
            for (int e = 0; e < 4; e++) d[bi][nt][e] = 0.0f;

    #pragma unroll
    for (int sp = 0; sp < 3; sp++) {
        const __nv_bfloat16* qt = sQT[sp];
        #pragma unroll
        for (int kc = 0; kc < 4; kc++) {
            #pragma unroll
            for (int nt = 0; nt < 8; nt++) {
                const int n = nt * 8 + g;
                const unsigned b0 = *reinterpret_cast<const unsigned*>(qt + n * QT_STRIDE + kc * 16 + tg * 2);
                const unsigned b1 = *reinterpret_cast<const unsigned*>(qt + n * QT_STRIDE + kc * 16 + tg * 2 + 8);
                mma_bf16(d[0][nt], af[0][kc], b0, b1);
                mma_bf16(d[1][nt], af[1][kc], b0, b1);
            }
        }
    }

    // Epilogue + bit-pack per block.
    //   af[bi][kc][0] <-> d[bi][2kc]   rows g   (cols 16kc+2tg,+1)
    //   af[bi][kc][1] <-> d[bi][2kc]   rows g+8
    //   af[bi][kc][2] <-> d[bi][2kc+1] rows g   (cols +8,+9)
    //   af[bi][kc][3] <-> d[bi][2kc+1] rows g+8
    #pragma unroll
    for (int bi = 0; bi < 2; bi++) {
        const int rb = row_base + bi * 16;
        float eg = 0.0f, eg8 = 0.0f;
        unsigned long long p0 = 0ull, p8 = 0ull;
        #pragma unroll
        for (int kc = 0; kc < 4; kc++) {
            const int c = kc * 16 + tg * 2;
            unsigned a;
            a = af[bi][kc][0];
            if (a & 0xFFFFu) { eg  += d[bi][2 * kc][0]; p0 |= 1ull << c; }
            if (a >> 16)     { eg  += d[bi][2 * kc][1]; p0 |= 1ull << (c + 1); }
            a = af[bi][kc][1];
            if (a & 0xFFFFu) { eg8 += d[bi][2 * kc][2]; p8 |= 1ull << c; }
            if (a >> 16)     { eg8 += d[bi][2 * kc][3]; p8 |= 1ull << (c + 1); }
            a = af[bi][kc][2];
            if (a & 0xFFFFu) { eg  += d[bi][2 * kc + 1][0]; p0 |= 1ull << (c + 8); }
            if (a >> 16)     { eg  += d[bi][2 * kc + 1][1]; p0 |= 1ull << (c + 9); }
            a = af[bi][kc][3];
            if (a & 0xFFFFu) { eg8 += d[bi][2 * kc + 1][2]; p8 |= 1ull << (c + 8); }
            if (a >> 16)     { eg8 += d[bi][2 * kc + 1][3]; p8 |= 1ull << (c + 9); }
        }
        eg  += __shfl_xor_sync(0xffffffffu, eg, 1);
        eg  += __shfl_xor_sync(0xffffffffu, eg, 2);
        eg8 += __shfl_xor_sync(0xffffffffu, eg8, 1);
        eg8 += __shfl_xor_sync(0xffffffffu, eg8, 2);
        p0 |= __shfl_xor_sync(0xffffffffu, p0, 1);
        p0 |= __shfl_xor_sync(0xffffffffu, p0, 2);
        p8 |= __shfl_xor_sync(0xffffffffu, p8, 1);
        p8 |= __shfl_xor_sync(0xffffffffu, p8, 2);
        if (tg == 0) {
            energies_out[rb + g]     = eg;
            energies_out[rb + 8 + g] = eg8;
            g_packed[rb + g]         = p0;
            g_packed[rb + 8 + g]     = p8;
        }
    }
}

// ---------------------------------------------------------------------------
// Kernel 2: mask[w,j,k] = u < exp((E[j+1]-E[j]) * (beta[j+1]-beta[j]))
// ---------------------------------------------------------------------------
__global__ void __launch_bounds__(256)
mask_kernel(const float* __restrict__ energies,
            const float* __restrict__ beta,
            const float* __restrict__ u) {
    const int idx = blockIdx.x * 256 + threadIdx.x;
    const int k = idx & 511;
    const int j = (idx >> 9) % 63;
    const int w = idx / (63 * 512);
    const float e1 = energies[(w * PL + j) * PK + k];
    const float e2 = energies[(w * PL + j + 1) * PK + k];
    const float db = beta[j + 1] - beta[j];
    const float delta = (e2 - e1) * db;
    g_mask[idx] = (u[idx] < expf(delta)) ? 1 : 0;
}

// ---------------------------------------------------------------------------
// Kernel 3: row-gather swap from PACKED bits (reads 8 MB instead of 268 MB).
//   out[w,0]   = mask[w,0]   ? states[w,1]   : states[w,0]
//   out[w,l>0] = mask[w,l-1] ? states[w,l-1] : states[w,l]
// Thread = 16 output floats (one 16-bit slice of a row).
// ---------------------------------------------------------------------------
__global__ void __launch_bounds__(256)
swap_kernel(float* __restrict__ out_states) {
    const int tid  = blockIdx.x * 256 + threadIdx.x;  // < TOTAL_ROWS * 4
    const int part = tid & 3;
    const int row  = tid >> 2;
    const int k = row & 511;
    const int l = (row >> 9) & 63;
    const int w = row >> 15;

    const int j = (l == 0) ? 0 : (l - 1);
    const bool m = g_mask[(w * 63 + j) * PK + k] != 0;
    int src;
    if (l == 0) src = m ? 1 : 0;
    else        src = m ? (l - 1) : l;

    const int src_row = (w * PL + src) * PK + k;
    const unsigned bits = (unsigned)(g_packed[src_row] >> (part * 16)) & 0xFFFFu;

    float4* dst = reinterpret_cast<float4*>(out_states + (((size_t)row) << 6) + (part << 4));
    #pragma unroll
    for (int q = 0; q < 4; q++) {
        float4 v;
        v.x = (bits >> (q * 4 + 0)) & 1u ? 1.0f : 0.0f;
        v.y = (bits >> (q * 4 + 1)) & 1u ? 1.0f : 0.0f;
        v.z = (bits >> (q * 4 + 2)) & 1u ? 1.0f : 0.0f;
        v.w = (bits >> (q * 4 + 3)) & 1u ? 1.0f : 0.0f;
        dst[q] = v;
    }
}

// ---------------------------------------------------------------------------

extern "C" void kernel_launch(void* const* d_in, const int* in_sizes, int n_in,
                              void* d_out, int out_size) {
    const float* states = (const float*)d_in[0];  // (32,64,512,64) f32
    const float* Q      = (const float*)d_in[1];  // (32,64,64) f32
    const float* beta   = (const float*)d_in[2];  // (64,) f32
    const float* u      = (const float*)d_in[3];  // (32,63,512) f32

    float* energies   = (float*)d_out;
    float* out_states = (float*)d_out + EN_ELEMS;

    dim3 egrid(128, PW);
    energies_kernel<<<egrid, 256>>>(states, Q, energies);

    mask_kernel<<<MASK_ELEMS / 256, 256>>>(energies, beta, u);

    swap_kernel<<<(TOTAL_ROWS * 4) / 256, 256>>>(out_states);
}